// round 15
// baseline (speedup 1.0000x reference)
#include <cuda_runtime.h>
#include <cuda_bf16.h>
#include <math.h>
#include <stdint.h>

#define DIM   1024
#define NHEAD 16
#define HDIM  64
#define BATCH 2
#define SEQ   2048
#define ROWS  (BATCH * SEQ)   // 4096

// ---------------------------------------------------------------------------
// Helpers (base-target PTX only: ldmatrix + mma.sync + cp.async)
// ---------------------------------------------------------------------------
__device__ __forceinline__ uint32_t smem_to_u32(const void* smem_ptr) {
    uint32_t addr;
    asm("{ .reg .u64 tmp; cvta.to.shared.u64 tmp, %1; cvt.u32.u64 %0, tmp; }"
        : "=r"(addr) : "l"(smem_ptr));
    return addr;
}

__device__ __forceinline__ void ldsm_x4(uint32_t addr, uint32_t* r) {
    asm volatile("ldmatrix.sync.aligned.m8n8.x4.shared.b16 {%0,%1,%2,%3}, [%4];"
        : "=r"(r[0]), "=r"(r[1]), "=r"(r[2]), "=r"(r[3]) : "r"(addr));
}

__device__ __forceinline__ void ldsm_x4_trans(uint32_t addr, uint32_t* r) {
    asm volatile("ldmatrix.sync.aligned.m8n8.x4.trans.shared.b16 {%0,%1,%2,%3}, [%4];"
        : "=r"(r[0]), "=r"(r[1]), "=r"(r[2]), "=r"(r[3]) : "r"(addr));
}

// D += A * B, bf16 inputs, fp32 accumulate (m16n8k16)
__device__ __forceinline__ void mma_bf16(float* d, const uint32_t* a,
                                         const uint32_t* b) {
    asm volatile(
        "mma.sync.aligned.m16n8k16.row.col.f32.bf16.bf16.f32 "
        "{%0,%1,%2,%3}, {%4,%5,%6,%7}, {%8,%9}, {%0,%1,%2,%3};"
        : "+f"(d[0]), "+f"(d[1]), "+f"(d[2]), "+f"(d[3])
        : "r"(a[0]), "r"(a[1]), "r"(a[2]), "r"(a[3]), "r"(b[0]), "r"(b[1]));
}

#define CP_ASYNC_16(saddr, gptr) \
    asm volatile("cp.async.cg.shared.global [%0], [%1], 16;" \
        :: "r"((uint32_t)(saddr)), "l"(gptr) : "memory")
#define CP_COMMIT() asm volatile("cp.async.commit_group;" ::: "memory")
#define CP_WAIT0()  asm volatile("cp.async.wait_group 0;" ::: "memory")

// raw exp2 (scores are pre-scaled by log2(e) via the Q projection epilogue)
__device__ __forceinline__ float ex2f(float x) {
    float y;
    asm("ex2.approx.f32 %0, %1;" : "=f"(y) : "f"(x));
    return y;
}

// hi/lo bf16 split of one fp32
__device__ __forceinline__ void bf16_split(float x, unsigned short& h,
                                           unsigned short& l) {
    __nv_bfloat16 hb = __float2bfloat16(x);
    __nv_bfloat16 lb = __float2bfloat16(x - __bfloat162float(hb));
    h = __bfloat16_as_ushort(hb);
    l = __bfloat16_as_ushort(lb);
}

// ---------------------------------------------------------------------------
// Scratch (allocation-free rule: __device__ globals)
// ---------------------------------------------------------------------------
__device__ __nv_bfloat16 g_Qh[ROWS * DIM], g_Ql[ROWS * DIM];
__device__ __nv_bfloat16 g_Kh[ROWS * DIM], g_Kl[ROWS * DIM];
__device__ __nv_bfloat16 g_Vh[ROWS * DIM], g_Vl[ROWS * DIM];
__device__ __nv_bfloat16 g_Xh[ROWS * DIM], g_Xl[ROWS * DIM];
__device__ __nv_bfloat16 g_Ah[ROWS * DIM], g_Al[ROWS * DIM];
__device__ __nv_bfloat16 g_Wh[4][DIM * DIM], g_Wl[4][DIM * DIM];  // q,k,v,o
__device__ float2 g_rope[SEQ * 32];   // (cos, sin) per (s, p)

// ---------------------------------------------------------------------------
// Rope table: one thread per (s, p) — 65536 distinct pairs.
// ---------------------------------------------------------------------------
__global__ void rope_table_kernel()
{
    int i = blockIdx.x * blockDim.x + threadIdx.x;
    int p = i & 31, s = i >> 5;
    float inv_freq = (float)exp((double)p * (-0.28782313662425574)); // 10000^(-p/32)
    float ang = (float)s * inv_freq;
    float sn, cs;
    sincosf(ang, &sn, &cs);
    g_rope[i] = make_float2(cs, sn);
}

// ---------------------------------------------------------------------------
// fp32 -> (bf16 hi, bf16 lo) splits
// ---------------------------------------------------------------------------
__global__ void split_kernel(const float* __restrict__ src,
                             __nv_bfloat16* __restrict__ hi,
                             __nv_bfloat16* __restrict__ lo, int n)
{
    int i = (blockIdx.x * blockDim.x + threadIdx.x) * 4;
    if (i >= n) return;
    float4 x = *(const float4*)(src + i);
    float xs[4] = {x.x, x.y, x.z, x.w};
    unsigned short hs[4], ls[4];
    #pragma unroll
    for (int k = 0; k < 4; k++) bf16_split(xs[k], hs[k], ls[k]);
    *(ushort4*)(hi + i) = make_ushort4(hs[0], hs[1], hs[2], hs[3]);
    *(ushort4*)(lo + i) = make_ushort4(ls[0], ls[1], ls[2], ls[3]);
}

__global__ void split_w4_kernel(const float* __restrict__ Wq,
                                const float* __restrict__ Wk,
                                const float* __restrict__ Wv,
                                const float* __restrict__ Wo)
{
    int i = (blockIdx.x * blockDim.x + threadIdx.x) * 4;
    const int w = i >> 20;
    const int j = i & ((DIM * DIM) - 1);
    const float* src = (w == 0) ? Wq : (w == 1) ? Wk : (w == 2) ? Wv : Wo;
    float4 x = *(const float4*)(src + j);
    float xs[4] = {x.x, x.y, x.z, x.w};
    unsigned short hs[4], ls[4];
    #pragma unroll
    for (int k = 0; k < 4; k++) bf16_split(xs[k], hs[k], ls[k]);
    *(ushort4*)(&g_Wh[0][0] + i) = make_ushort4(hs[0], hs[1], hs[2], hs[3]);
    *(ushort4*)(&g_Wl[0][0] + i) = make_ushort4(ls[0], ls[1], ls[2], ls[3]);
}

// ---------------------------------------------------------------------------
// HMMA NT GEMM, cp.async double-buffered (R15): C = A*B^T.
// Stage layout identical to R14 (4 tiles of 128 rows x 40-elem pitch), so all
// ldmatrix offsets are the verified ones; the register staging + store phase
// and one barrier per chunk are gone.
// MODE 0: fp32 C. MODE 1: bf16 hi/lo C. MODE 2: RoPE+scale+hi/lo C.
// ---------------------------------------------------------------------------
#define BK          32
#define PITCH       40
#define TILE_B      (128 * PITCH * 2)           // 10240 bytes per tile
#define STAGE_BYTES (4 * TILE_B)                // 40960
#define SMEM_DYN    (2 * STAGE_BYTES)           // 81920

template <int MODE>
__device__ __forceinline__ void hmma_gemm_body(const __nv_bfloat16* __restrict__ Ahg,
                                               const __nv_bfloat16* __restrict__ Alg,
                                               const __nv_bfloat16* __restrict__ Bhg,
                                               const __nv_bfloat16* __restrict__ Blg,
                                               float* __restrict__ C,
                                               __nv_bfloat16* __restrict__ Ch,
                                               __nv_bfloat16* __restrict__ Cl,
                                               float qscale)
{
    extern __shared__ __nv_bfloat16 sm[];
    const uint32_t smbase = smem_to_u32(sm);

    const int tid  = threadIdx.x;
    const int wid  = tid >> 5;
    const int lane = tid & 31;
    const int tm   = blockIdx.y * 128;
    const int tn   = blockIdx.x * 128;

    // cp.async mapping: thread -> (row = tid>>1, 32B half = (tid&1)*32) per tile
    const int lrow  = tid >> 1;
    const int lhalf = (tid & 1) * 32;
    const char* gbase[4] = {
        (const char*)(Ahg + (size_t)(tm + lrow) * DIM) + lhalf,
        (const char*)(Alg + (size_t)(tm + lrow) * DIM) + lhalf,
        (const char*)(Bhg + (size_t)(tn + lrow) * DIM) + lhalf,
        (const char*)(Blg + (size_t)(tn + lrow) * DIM) + lhalf
    };
    const uint32_t sdst = lrow * (PITCH * 2) + lhalf;

    auto issue_chunk = [&](int c, int s) {
        const size_t go = (size_t)c * (BK * 2);   // bytes along k
        const uint32_t sb = smbase + s * STAGE_BYTES + sdst;
        #pragma unroll
        for (int t = 0; t < 4; t++) {
            const char* gp = gbase[t] + go;
            CP_ASYNC_16(sb + t * TILE_B,      gp);
            CP_ASYNC_16(sb + t * TILE_B + 16, gp + 16);
        }
    };

    const int wm = (wid & 3) * 32;
    const int wn = (wid >> 2) * 64;

    const uint32_t a_off = (uint32_t)(wm + (lane & 15)) * 80 + ((lane >> 4) & 1) * 16;
    const uint32_t b_off = (uint32_t)(wn + (lane & 7) + ((lane >> 4) & 1) * 8) * 80
                         + ((lane >> 3) & 1) * 16;

    float acc[2][8][4];
    #pragma unroll
    for (int i = 0; i < 2; i++)
        #pragma unroll
        for (int j = 0; j < 8; j++)
            #pragma unroll
            for (int k = 0; k < 4; k++) acc[i][j][k] = 0.0f;

    issue_chunk(0, 0);
    CP_COMMIT();

    const int NCH = DIM / BK;   // 32
    #pragma unroll 1
    for (int c = 0; c < NCH; c++) {
        const int s = c & 1;
        CP_WAIT0();
        __syncthreads();
        if (c + 1 < NCH) { issue_chunk(c + 1, s ^ 1); CP_COMMIT(); }

        const uint32_t sb = smbase + s * STAGE_BYTES;
        #pragma unroll
        for (int ks = 0; ks < 2; ks++) {
            uint32_t ah[2][4], al_[2][4], bh[8][2], bl_[8][2];
            #pragma unroll
            for (int mt = 0; mt < 2; mt++) {
                ldsm_x4(sb + a_off + mt * 1280 + ks * 32, ah[mt]);
                ldsm_x4(sb + TILE_B + a_off + mt * 1280 + ks * 32, al_[mt]);
            }
            #pragma unroll
            for (int nt2 = 0; nt2 < 4; nt2++) {
                uint32_t t[4];
                ldsm_x4(sb + 2 * TILE_B + b_off + nt2 * 1280 + ks * 32, t);
                bh[2*nt2][0] = t[0]; bh[2*nt2][1] = t[1];
                bh[2*nt2+1][0] = t[2]; bh[2*nt2+1][1] = t[3];
                ldsm_x4(sb + 3 * TILE_B + b_off + nt2 * 1280 + ks * 32, t);
                bl_[2*nt2][0] = t[0]; bl_[2*nt2][1] = t[1];
                bl_[2*nt2+1][0] = t[2]; bl_[2*nt2+1][1] = t[3];
            }
            #pragma unroll
            for (int mt = 0; mt < 2; mt++)
                #pragma unroll
                for (int nt = 0; nt < 8; nt++) {
                    mma_bf16(acc[mt][nt], ah[mt],  bh[nt]);
                    mma_bf16(acc[mt][nt], ah[mt],  bl_[nt]);
                    mma_bf16(acc[mt][nt], al_[mt], bh[nt]);
                }
        }
        __syncthreads();   // all reads of stage s done before it is refilled
    }

    if (MODE == 2) {
        #pragma unroll
        for (int mt = 0; mt < 2; mt++) {
            const int r0 = tm + wm + mt * 16 + (lane >> 2);
            const int s0 = r0 & (SEQ - 1);
            const int s1 = (r0 + 8) & (SEQ - 1);
            #pragma unroll
            for (int nt = 0; nt < 4; nt++) {
                const int p   = nt * 8 + (lane & 3) * 2;
                const int col = tn + wn + p;
                const float2 c0a = g_rope[s0 * 32 + p];
                const float2 c0b = g_rope[s0 * 32 + p + 1];
                const float2 c1a = g_rope[s1 * 32 + p];
                const float2 c1b = g_rope[s1 * 32 + p + 1];
                float y[2][4];
                y[0][0] = (acc[mt][nt][0] * c0a.x - acc[mt][nt+4][0] * c0a.y) * qscale;
                y[0][1] = (acc[mt][nt][1] * c0b.x - acc[mt][nt+4][1] * c0b.y) * qscale;
                y[0][2] = (acc[mt][nt+4][0] * c0a.x + acc[mt][nt][0] * c0a.y) * qscale;
                y[0][3] = (acc[mt][nt+4][1] * c0b.x + acc[mt][nt][1] * c0b.y) * qscale;
                y[1][0] = (acc[mt][nt][2] * c1a.x - acc[mt][nt+4][2] * c1a.y) * qscale;
                y[1][1] = (acc[mt][nt][3] * c1b.x - acc[mt][nt+4][3] * c1b.y) * qscale;
                y[1][2] = (acc[mt][nt+4][2] * c1a.x + acc[mt][nt][2] * c1a.y) * qscale;
                y[1][3] = (acc[mt][nt+4][3] * c1b.x + acc[mt][nt][3] * c1b.y) * qscale;
                #pragma unroll
                for (int rr = 0; rr < 2; rr++) {
                    const size_t rbase = (size_t)(r0 + rr * 8) * DIM;
                    unsigned short h0, l0, h1, l1;
                    bf16_split(y[rr][0], h0, l0);
                    bf16_split(y[rr][1], h1, l1);
                    *(ushort2*)(Ch + rbase + col)      = make_ushort2(h0, h1);
                    *(ushort2*)(Cl + rbase + col)      = make_ushort2(l0, l1);
                    bf16_split(y[rr][2], h0, l0);
                    bf16_split(y[rr][3], h1, l1);
                    *(ushort2*)(Ch + rbase + col + 32) = make_ushort2(h0, h1);
                    *(ushort2*)(Cl + rbase + col + 32) = make_ushort2(l0, l1);
                }
            }
        }
        return;
    }

    #pragma unroll
    for (int mt = 0; mt < 2; mt++) {
        const int r0 = tm + wm + mt * 16 + (lane >> 2);
        #pragma unroll
        for (int nt = 0; nt < 8; nt++) {
            const int col = tn + wn + nt * 8 + (lane & 3) * 2;
            if (MODE == 0) {
                *(float2*)(C + (size_t)r0 * DIM + col) =
                    make_float2(acc[mt][nt][0], acc[mt][nt][1]);
                *(float2*)(C + (size_t)(r0 + 8) * DIM + col) =
                    make_float2(acc[mt][nt][2], acc[mt][nt][3]);
            } else {
                unsigned short h0, l0, h1, l1;
                bf16_split(acc[mt][nt][0], h0, l0);
                bf16_split(acc[mt][nt][1], h1, l1);
                *(ushort2*)(Ch + (size_t)r0 * DIM + col) = make_ushort2(h0, h1);
                *(ushort2*)(Cl + (size_t)r0 * DIM + col) = make_ushort2(l0, l1);
                bf16_split(acc[mt][nt][2], h0, l0);
                bf16_split(acc[mt][nt][3], h1, l1);
                *(ushort2*)(Ch + (size_t)(r0 + 8) * DIM + col) = make_ushort2(h0, h1);
                *(ushort2*)(Cl + (size_t)(r0 + 8) * DIM + col) = make_ushort2(l0, l1);
            }
        }
    }
}

// Q scale folds 1/sqrt(HDIM) AND log2(e): flash computes exp2(s) == exp(q.k/8).
#define QSCALE (0.125f * 1.4426950408889634f)

__global__ void __launch_bounds__(256, 1) hmma_qkv_kernel()
{
    const int z = blockIdx.z;
    if (z == 0)
        hmma_gemm_body<2>(g_Xh, g_Xl, g_Wh[0], g_Wl[0], nullptr, g_Qh, g_Ql, QSCALE);
    else if (z == 1)
        hmma_gemm_body<2>(g_Xh, g_Xl, g_Wh[1], g_Wl[1], nullptr, g_Kh, g_Kl, 1.0f);
    else
        hmma_gemm_body<1>(g_Xh, g_Xl, g_Wh[2], g_Wl[2], nullptr, g_Vh, g_Vl, 1.0f);
}

__global__ void __launch_bounds__(256, 1) hmma_oproj_kernel(float* __restrict__ out)
{
    hmma_gemm_body<0>(g_Ah, g_Al, g_Wh[3], g_Wl[3], out, nullptr, nullptr, 1.0f);
}

// ---------------------------------------------------------------------------
// HMMA flash attention (R15): softmax pack interleaved with PV MMAs so MUFU /
// split ALU work overlaps the tensor pipe; scores arrive in log2 domain.
// ---------------------------------------------------------------------------
#define FP          72
#define FQT         (128 * FP)
#define FKT_B       (64 * FP * 2)               // 9216 bytes
#define STG_B       (4 * FKT_B)                 // 36864 bytes
#define FSMEM_BYTES (2 * FQT * 2 + 2 * STG_B)   // 110592

__global__ void __launch_bounds__(256, 1) flash_hmma_kernel()
{
    extern __shared__ __nv_bfloat16 fsm[];
    __nv_bfloat16* sQh = fsm;
    __nv_bfloat16* sQl = fsm + FQT;

    const int tid  = threadIdx.x;
    const int wid  = tid >> 5;
    const int lane = tid & 31;
    const int qt = blockIdx.x, h = blockIdx.y, b = blockIdx.z;
    const int q0 = b * SEQ + qt * 128;

    const uint32_t uQh = smem_to_u32(sQh);
    const uint32_t uQl = uQh + FQT * 2;
    uint32_t uStage[2];
    uStage[0] = uQh + 2 * FQT * 2;
    uStage[1] = uStage[0] + STG_B;

    // ---- load Q tile (persistent)
    #pragma unroll
    for (int t = tid; t < 1024; t += 256) {
        int row = t >> 3, seg = t & 7;
        size_t go = (size_t)(q0 + row) * DIM + h * HDIM + seg * 8;
        *(uint4*)(sQh + row * FP + seg * 8) = *(const uint4*)(g_Qh + go);
        *(uint4*)(sQl + row * FP + seg * 8) = *(const uint4*)(g_Ql + go);
    }

    // cp.async K/V stage loader
    const int crow = tid >> 2;
    const int cofs = (tid & 3) * 32;
    const __nv_bfloat16* gsrc[4] = { g_Kh, g_Kl, g_Vh, g_Vl };
    auto issue_stage = [&](int kt, int s) {
        const size_t go = (size_t)(b * SEQ + kt * 64 + crow) * DIM + h * HDIM;
        #pragma unroll
        for (int t = 0; t < 4; t++) {
            const char* gp = (const char*)(gsrc[t] + go) + cofs;
            uint32_t sp = uStage[s] + t * FKT_B + crow * 144 + cofs;
            CP_ASYNC_16(sp,      gp);
            CP_ASYNC_16(sp + 16, gp + 16);
        }
    };

    const int wm = wid * 16;
    const uint32_t a_off   = (uint32_t)(wm + (lane & 15)) * 144 + ((lane >> 4) & 1) * 16;
    const uint32_t b_off_k = (uint32_t)((lane & 7) + ((lane >> 4) & 1) * 8) * 144
                           + ((lane >> 3) & 1) * 16;
    const uint32_t b_off_v = (uint32_t)((lane & 7) + ((lane >> 3) & 1) * 8) * 144
                           + ((lane >> 4) & 1) * 16;

    float o[8][4];
    #pragma unroll
    for (int i = 0; i < 8; i++)
        #pragma unroll
        for (int j = 0; j < 4; j++) o[i][j] = 0.0f;
    float l0 = 0.0f, l1 = 0.0f;

    issue_stage(0, 0);
    CP_COMMIT();

    #pragma unroll 1
    for (int kt = 0; kt < SEQ / 64; kt++) {
        const int s = kt & 1;
        CP_WAIT0();
        __syncthreads();
        if (kt + 1 < SEQ / 64) { issue_stage(kt + 1, s ^ 1); CP_COMMIT(); }

        const uint32_t uKh = uStage[s];
        const uint32_t uKl = uStage[s] + FKT_B;
        const uint32_t uVh = uStage[s] + 2 * FKT_B;
        const uint32_t uVl = uStage[s] + 3 * FKT_B;

        // ---- S = Q K^T (3 split passes); scores in log2 domain
        float sc[8][4];
        #pragma unroll
        for (int i = 0; i < 8; i++)
            #pragma unroll
            for (int j = 0; j < 4; j++) sc[i][j] = 0.0f;

        #pragma unroll
        for (int ks = 0; ks < 4; ks++) {
            uint32_t ah[4], al[4];
            ldsm_x4(uQh + a_off + ks * 32, ah);
            ldsm_x4(uQl + a_off + ks * 32, al);
            #pragma unroll
            for (int nt2 = 0; nt2 < 4; nt2++) {
                uint32_t th[4], tl[4];
                ldsm_x4(uKh + b_off_k + nt2 * 2304 + ks * 32, th);
                ldsm_x4(uKl + b_off_k + nt2 * 2304 + ks * 32, tl);
                mma_bf16(sc[2*nt2],   ah, th);     mma_bf16(sc[2*nt2],   ah, tl);
                mma_bf16(sc[2*nt2],   al, th);
                mma_bf16(sc[2*nt2+1], ah, th + 2); mma_bf16(sc[2*nt2+1], ah, tl + 2);
                mma_bf16(sc[2*nt2+1], al, th + 2);
            }
        }

        // ---- interleaved softmax pack + PV: exp/split for slice ks issue
        //      just before PV-MMA ks, so ks+1's MUFU overlaps ks's tensor work
        float rs0 = 0.0f, rs1 = 0.0f;
        #pragma unroll
        for (int ks = 0; ks < 4; ks++) {
            uint32_t aPh[4], aPl[4];
            #pragma unroll
            for (int hh = 0; hh < 2; hh++) {
                const int nf = 2 * ks + hh;
                float e00 = ex2f(sc[nf][0]);
                float e01 = ex2f(sc[nf][1]);
                float e10 = ex2f(sc[nf][2]);
                float e11 = ex2f(sc[nf][3]);
                rs0 += e00 + e01;
                rs1 += e10 + e11;
                unsigned short h00, l00, h01, l01, h10, l10, h11, l11;
                bf16_split(e00, h00, l00); bf16_split(e01, h01, l01);
                bf16_split(e10, h10, l10); bf16_split(e11, h11, l11);
                aPh[2*hh]   = ((uint32_t)h01 << 16) | h00;
                aPh[2*hh+1] = ((uint32_t)h11 << 16) | h10;
                aPl[2*hh]   = ((uint32_t)l01 << 16) | l00;
                aPl[2*hh+1] = ((uint32_t)l11 << 16) | l10;
            }
            #pragma unroll
            for (int nt2 = 0; nt2 < 4; nt2++) {
                uint32_t th[4], tl[4];
                ldsm_x4_trans(uVh + b_off_v + ks * 2304 + nt2 * 32, th);
                ldsm_x4_trans(uVl + b_off_v + ks * 2304 + nt2 * 32, tl);
                mma_bf16(o[2*nt2],   aPh, th);     mma_bf16(o[2*nt2],   aPh, tl);
                mma_bf16(o[2*nt2],   aPl, th);
                mma_bf16(o[2*nt2+1], aPh, th + 2); mma_bf16(o[2*nt2+1], aPh, tl + 2);
                mma_bf16(o[2*nt2+1], aPl, th + 2);
            }
        }
        rs0 += __shfl_xor_sync(0xffffffffu, rs0, 1);
        rs0 += __shfl_xor_sync(0xffffffffu, rs0, 2);
        rs1 += __shfl_xor_sync(0xffffffffu, rs1, 1);
        rs1 += __shfl_xor_sync(0xffffffffu, rs1, 2);
        l0 += rs0;
        l1 += rs1;
    }

    // ---- epilogue: normalize, write bf16 hi/lo attention output
    const float inv0 = 1.0f / l0, inv1 = 1.0f / l1;
    const int r0 = q0 + wm + (lane >> 2);
    #pragma unroll
    for (int nf = 0; nf < 8; nf++) {
        const int col = h * HDIM + nf * 8 + (lane & 3) * 2;
        unsigned short h0, lo0, h1, lo1;
        bf16_split(o[nf][0] * inv0, h0, lo0);
        bf16_split(o[nf][1] * inv0, h1, lo1);
        *(ushort2*)(g_Ah + (size_t)r0 * DIM + col) = make_ushort2(h0, h1);
        *(ushort2*)(g_Al + (size_t)r0 * DIM + col) = make_ushort2(lo0, lo1);
        bf16_split(o[nf][2] * inv1, h0, lo0);
        bf16_split(o[nf][3] * inv1, h1, lo1);
        *(ushort2*)(g_Ah + (size_t)(r0 + 8) * DIM + col) = make_ushort2(h0, h1);
        *(ushort2*)(g_Al + (size_t)(r0 + 8) * DIM + col) = make_ushort2(lo0, lo1);
    }
}

// ---------------------------------------------------------------------------
extern "C" void kernel_launch(void* const* d_in, const int* in_sizes, int n_in,
                              void* d_out, int out_size)
{
    const float* x  = (const float*)d_in[0];
    const float* Wq = (const float*)d_in[1];
    const float* Wk = (const float*)d_in[2];
    const float* Wv = (const float*)d_in[3];
    const float* Wo = (const float*)d_in[4];
    float* out = (float*)d_out;

    (void)in_sizes; (void)n_in; (void)out_size;

    cudaFuncSetAttribute(hmma_qkv_kernel,
                         cudaFuncAttributeMaxDynamicSharedMemorySize, SMEM_DYN);
    cudaFuncSetAttribute(hmma_oproj_kernel,
                         cudaFuncAttributeMaxDynamicSharedMemorySize, SMEM_DYN);
    cudaFuncSetAttribute(flash_hmma_kernel,
                         cudaFuncAttributeMaxDynamicSharedMemorySize, FSMEM_BYTES);

    __nv_bfloat16 *xh, *xl;
    cudaGetSymbolAddress((void**)&xh, g_Xh);
    cudaGetSymbolAddress((void**)&xl, g_Xl);

    const int nX = ROWS * DIM;      // 4M

    // 0) Rope cos/sin table
    rope_table_kernel<<<SEQ * 32 / 256, 256>>>();

    // 1) Split inputs into bf16 hi/lo
    split_kernel<<<nX / 4 / 256, 256>>>(x, xh, xl, nX);
    split_w4_kernel<<<4 * DIM * DIM / 4 / 256, 256>>>(Wq, Wk, Wv, Wo);

    // 2) Q,K,V projections; Q/K epilogues apply RoPE+scale+split in-register
    hmma_qkv_kernel<<<dim3(DIM / 128, ROWS / 128, 3), 256, SMEM_DYN>>>();

    // 3) Attention on HMMA
    flash_hmma_kernel<<<dim3(SEQ / 128, NHEAD, BATCH), 256, FSMEM_BYTES>>>();

    // 4) Output projection
    hmma_oproj_kernel<<<dim3(DIM / 128, ROWS / 128), 256, SMEM_DYN>>>(out);
}

// round 16
// speedup vs baseline: 1.1380x; 1.1380x over previous
#include <cuda_runtime.h>
#include <cuda_bf16.h>
#include <math.h>
#include <stdint.h>

#define DIM   1024
#define NHEAD 16
#define HDIM  64
#define BATCH 2
#define SEQ   2048
#define ROWS  (BATCH * SEQ)   // 4096

// ---------------------------------------------------------------------------
// Helpers (base-target PTX only: ldmatrix + mma.sync + cp.async)
// ---------------------------------------------------------------------------
__device__ __forceinline__ uint32_t smem_to_u32(const void* smem_ptr) {
    uint32_t addr;
    asm("{ .reg .u64 tmp; cvta.to.shared.u64 tmp, %1; cvt.u32.u64 %0, tmp; }"
        : "=r"(addr) : "l"(smem_ptr));
    return addr;
}

__device__ __forceinline__ void ldsm_x4(uint32_t addr, uint32_t* r) {
    asm volatile("ldmatrix.sync.aligned.m8n8.x4.shared.b16 {%0,%1,%2,%3}, [%4];"
        : "=r"(r[0]), "=r"(r[1]), "=r"(r[2]), "=r"(r[3]) : "r"(addr));
}

__device__ __forceinline__ void ldsm_x4_trans(uint32_t addr, uint32_t* r) {
    asm volatile("ldmatrix.sync.aligned.m8n8.x4.trans.shared.b16 {%0,%1,%2,%3}, [%4];"
        : "=r"(r[0]), "=r"(r[1]), "=r"(r[2]), "=r"(r[3]) : "r"(addr));
}

// D += A * B, bf16 inputs, fp32 accumulate (m16n8k16)
__device__ __forceinline__ void mma_bf16(float* d, const uint32_t* a,
                                         const uint32_t* b) {
    asm volatile(
        "mma.sync.aligned.m16n8k16.row.col.f32.bf16.bf16.f32 "
        "{%0,%1,%2,%3}, {%4,%5,%6,%7}, {%8,%9}, {%0,%1,%2,%3};"
        : "+f"(d[0]), "+f"(d[1]), "+f"(d[2]), "+f"(d[3])
        : "r"(a[0]), "r"(a[1]), "r"(a[2]), "r"(a[3]), "r"(b[0]), "r"(b[1]));
}

#define CP_ASYNC_16(saddr, gptr) \
    asm volatile("cp.async.cg.shared.global [%0], [%1], 16;" \
        :: "r"((uint32_t)(saddr)), "l"(gptr) : "memory")
#define CP_COMMIT() asm volatile("cp.async.commit_group;" ::: "memory")
#define CP_WAIT0()  asm volatile("cp.async.wait_group 0;" ::: "memory")

// raw exp2 (scores are pre-scaled by log2(e) via the Q projection epilogue)
__device__ __forceinline__ float ex2f(float x) {
    float y;
    asm("ex2.approx.f32 %0, %1;" : "=f"(y) : "f"(x));
    return y;
}

// hi/lo bf16 split of one fp32
__device__ __forceinline__ void bf16_split(float x, unsigned short& h,
                                           unsigned short& l) {
    __nv_bfloat16 hb = __float2bfloat16(x);
    __nv_bfloat16 lb = __float2bfloat16(x - __bfloat162float(hb));
    h = __bfloat16_as_ushort(hb);
    l = __bfloat16_as_ushort(lb);
}

// ---------------------------------------------------------------------------
// Scratch (allocation-free rule: __device__ globals)
// ---------------------------------------------------------------------------
__device__ __nv_bfloat16 g_Qh[ROWS * DIM], g_Ql[ROWS * DIM];
__device__ __nv_bfloat16 g_Kh[ROWS * DIM], g_Kl[ROWS * DIM];
__device__ __nv_bfloat16 g_Vh[ROWS * DIM], g_Vl[ROWS * DIM];
__device__ __nv_bfloat16 g_Xh[ROWS * DIM], g_Xl[ROWS * DIM];
__device__ __nv_bfloat16 g_Ah[ROWS * DIM], g_Al[ROWS * DIM];
__device__ __nv_bfloat16 g_Wh[4][DIM * DIM], g_Wl[4][DIM * DIM];  // q,k,v,o
__device__ float2 g_rope[SEQ * 32];   // (cos, sin) per (s, p)

// ---------------------------------------------------------------------------
// Rope table: one thread per (s, p) — 65536 distinct pairs.
// ---------------------------------------------------------------------------
__global__ void rope_table_kernel()
{
    int i = blockIdx.x * blockDim.x + threadIdx.x;
    int p = i & 31, s = i >> 5;
    float inv_freq = (float)exp((double)p * (-0.28782313662425574)); // 10000^(-p/32)
    float ang = (float)s * inv_freq;
    float sn, cs;
    sincosf(ang, &sn, &cs);
    g_rope[i] = make_float2(cs, sn);
}

// ---------------------------------------------------------------------------
// fp32 -> (bf16 hi, bf16 lo) splits
// ---------------------------------------------------------------------------
__global__ void split_kernel(const float* __restrict__ src,
                             __nv_bfloat16* __restrict__ hi,
                             __nv_bfloat16* __restrict__ lo, int n)
{
    int i = (blockIdx.x * blockDim.x + threadIdx.x) * 4;
    if (i >= n) return;
    float4 x = *(const float4*)(src + i);
    float xs[4] = {x.x, x.y, x.z, x.w};
    unsigned short hs[4], ls[4];
    #pragma unroll
    for (int k = 0; k < 4; k++) bf16_split(xs[k], hs[k], ls[k]);
    *(ushort4*)(hi + i) = make_ushort4(hs[0], hs[1], hs[2], hs[3]);
    *(ushort4*)(lo + i) = make_ushort4(ls[0], ls[1], ls[2], ls[3]);
}

__global__ void split_w4_kernel(const float* __restrict__ Wq,
                                const float* __restrict__ Wk,
                                const float* __restrict__ Wv,
                                const float* __restrict__ Wo)
{
    int i = (blockIdx.x * blockDim.x + threadIdx.x) * 4;
    const int w = i >> 20;
    const int j = i & ((DIM * DIM) - 1);
    const float* src = (w == 0) ? Wq : (w == 1) ? Wk : (w == 2) ? Wv : Wo;
    float4 x = *(const float4*)(src + j);
    float xs[4] = {x.x, x.y, x.z, x.w};
    unsigned short hs[4], ls[4];
    #pragma unroll
    for (int k = 0; k < 4; k++) bf16_split(xs[k], hs[k], ls[k]);
    *(ushort4*)(&g_Wh[0][0] + i) = make_ushort4(hs[0], hs[1], hs[2], hs[3]);
    *(ushort4*)(&g_Wl[0][0] + i) = make_ushort4(ls[0], ls[1], ls[2], ls[3]);
}

// ---------------------------------------------------------------------------
// HMMA NT GEMM — exact R14 body (register prefetch; measured 238us qkv).
// MODE 0: fp32 C. MODE 1: bf16 hi/lo C. MODE 2: RoPE+scale+hi/lo C.
// ---------------------------------------------------------------------------
#define BK          32
#define PITCH       40
#define TILE_ELEMS  (128 * PITCH)
#define STAGE_ELEMS (4 * TILE_ELEMS)
#define STAGE_BYTES (STAGE_ELEMS * 2)           // 40960
#define SMEM_DYN    (2 * STAGE_BYTES)           // 81920

template <int MODE>
__device__ __forceinline__ void hmma_gemm_body(const __nv_bfloat16* __restrict__ Ahg,
                                               const __nv_bfloat16* __restrict__ Alg,
                                               const __nv_bfloat16* __restrict__ Bhg,
                                               const __nv_bfloat16* __restrict__ Blg,
                                               float* __restrict__ C,
                                               __nv_bfloat16* __restrict__ Ch,
                                               __nv_bfloat16* __restrict__ Cl,
                                               float qscale)
{
    extern __shared__ __nv_bfloat16 sm[];
    const uint32_t smbase = smem_to_u32(sm);

    const int tid  = threadIdx.x;
    const int wid  = tid >> 5;
    const int lane = tid & 31;
    const int tm   = blockIdx.y * 128;
    const int tn   = blockIdx.x * 128;

    const int grow = tid >> 2;
    const int gseg = tid & 3;
    const __nv_bfloat16* pAh = Ahg + (size_t)(tm + grow) * DIM + gseg * 8;
    const __nv_bfloat16* pAl = Alg + (size_t)(tm + grow) * DIM + gseg * 8;
    const __nv_bfloat16* pBh = Bhg + (size_t)(tn + grow) * DIM + gseg * 8;
    const __nv_bfloat16* pBl = Blg + (size_t)(tn + grow) * DIM + gseg * 8;
    const size_t rstep = (size_t)64 * DIM;
    const int so = grow * PITCH + gseg * 8;

    const int wm = (wid & 3) * 32;
    const int wn = (wid >> 2) * 64;

    const uint32_t a_off = (uint32_t)(wm + (lane & 15)) * 80 + ((lane >> 4) & 1) * 16;
    const uint32_t b_off = (uint32_t)(wn + (lane & 7) + ((lane >> 4) & 1) * 8) * 80
                         + ((lane >> 3) & 1) * 16;

    float acc[2][8][4];
    #pragma unroll
    for (int i = 0; i < 2; i++)
        #pragma unroll
        for (int j = 0; j < 8; j++)
            #pragma unroll
            for (int k = 0; k < 4; k++) acc[i][j][k] = 0.0f;

    uint4 v[8];
    v[0] = *(const uint4*)(pAh);  v[1] = *(const uint4*)(pAh + rstep);
    v[2] = *(const uint4*)(pAl);  v[3] = *(const uint4*)(pAl + rstep);
    v[4] = *(const uint4*)(pBh);  v[5] = *(const uint4*)(pBh + rstep);
    v[6] = *(const uint4*)(pBl);  v[7] = *(const uint4*)(pBl + rstep);
    {
        __nv_bfloat16* st = sm;
        *(uint4*)(st + so)                           = v[0];
        *(uint4*)(st + so + 64 * PITCH)              = v[1];
        *(uint4*)(st + TILE_ELEMS + so)              = v[2];
        *(uint4*)(st + TILE_ELEMS + so + 64*PITCH)   = v[3];
        *(uint4*)(st + 2*TILE_ELEMS + so)            = v[4];
        *(uint4*)(st + 2*TILE_ELEMS + so + 64*PITCH) = v[5];
        *(uint4*)(st + 3*TILE_ELEMS + so)            = v[6];
        *(uint4*)(st + 3*TILE_ELEMS + so + 64*PITCH) = v[7];
    }
    __syncthreads();

    const int NCH = DIM / BK;   // 32
    #pragma unroll 1
    for (int c = 0; c < NCH; c++) {
        const int s = c & 1;
        if (c + 1 < NCH) {
            const size_t k = (size_t)(c + 1) * BK;
            v[0] = *(const uint4*)(pAh + k);  v[1] = *(const uint4*)(pAh + rstep + k);
            v[2] = *(const uint4*)(pAl + k);  v[3] = *(const uint4*)(pAl + rstep + k);
            v[4] = *(const uint4*)(pBh + k);  v[5] = *(const uint4*)(pBh + rstep + k);
            v[6] = *(const uint4*)(pBl + k);  v[7] = *(const uint4*)(pBl + rstep + k);
        }

        const uint32_t sb = smbase + s * STAGE_BYTES;
        #pragma unroll
        for (int ks = 0; ks < 2; ks++) {
            uint32_t ah[2][4], al_[2][4], bh[8][2], bl_[8][2];
            #pragma unroll
            for (int mt = 0; mt < 2; mt++) {
                ldsm_x4(sb + a_off + mt * 1280 + ks * 32, ah[mt]);
                ldsm_x4(sb + 10240 + a_off + mt * 1280 + ks * 32, al_[mt]);
            }
            #pragma unroll
            for (int nt2 = 0; nt2 < 4; nt2++) {
                uint32_t t[4];
                ldsm_x4(sb + 20480 + b_off + nt2 * 1280 + ks * 32, t);
                bh[2*nt2][0] = t[0]; bh[2*nt2][1] = t[1];
                bh[2*nt2+1][0] = t[2]; bh[2*nt2+1][1] = t[3];
                ldsm_x4(sb + 30720 + b_off + nt2 * 1280 + ks * 32, t);
                bl_[2*nt2][0] = t[0]; bl_[2*nt2][1] = t[1];
                bl_[2*nt2+1][0] = t[2]; bl_[2*nt2+1][1] = t[3];
            }
            #pragma unroll
            for (int mt = 0; mt < 2; mt++)
                #pragma unroll
                for (int nt = 0; nt < 8; nt++) {
                    mma_bf16(acc[mt][nt], ah[mt],  bh[nt]);
                    mma_bf16(acc[mt][nt], ah[mt],  bl_[nt]);
                    mma_bf16(acc[mt][nt], al_[mt], bh[nt]);
                }
        }

        if (c + 1 < NCH) {
            __nv_bfloat16* st = sm + (s ^ 1) * STAGE_ELEMS;
            *(uint4*)(st + so)                           = v[0];
            *(uint4*)(st + so + 64 * PITCH)              = v[1];
            *(uint4*)(st + TILE_ELEMS + so)              = v[2];
            *(uint4*)(st + TILE_ELEMS + so + 64*PITCH)   = v[3];
            *(uint4*)(st + 2*TILE_ELEMS + so)            = v[4];
            *(uint4*)(st + 2*TILE_ELEMS + so + 64*PITCH) = v[5];
            *(uint4*)(st + 3*TILE_ELEMS + so)            = v[6];
            *(uint4*)(st + 3*TILE_ELEMS + so + 64*PITCH) = v[7];
            __syncthreads();
        }
    }

    if (MODE == 2) {
        #pragma unroll
        for (int mt = 0; mt < 2; mt++) {
            const int r0 = tm + wm + mt * 16 + (lane >> 2);
            const int s0 = r0 & (SEQ - 1);
            const int s1 = (r0 + 8) & (SEQ - 1);
            #pragma unroll
            for (int nt = 0; nt < 4; nt++) {
                const int p   = nt * 8 + (lane & 3) * 2;
                const int col = tn + wn + p;
                const float2 c0a = g_rope[s0 * 32 + p];
                const float2 c0b = g_rope[s0 * 32 + p + 1];
                const float2 c1a = g_rope[s1 * 32 + p];
                const float2 c1b = g_rope[s1 * 32 + p + 1];
                float y[2][4];
                y[0][0] = (acc[mt][nt][0] * c0a.x - acc[mt][nt+4][0] * c0a.y) * qscale;
                y[0][1] = (acc[mt][nt][1] * c0b.x - acc[mt][nt+4][1] * c0b.y) * qscale;
                y[0][2] = (acc[mt][nt+4][0] * c0a.x + acc[mt][nt][0] * c0a.y) * qscale;
                y[0][3] = (acc[mt][nt+4][1] * c0b.x + acc[mt][nt][1] * c0b.y) * qscale;
                y[1][0] = (acc[mt][nt][2] * c1a.x - acc[mt][nt+4][2] * c1a.y) * qscale;
                y[1][1] = (acc[mt][nt][3] * c1b.x - acc[mt][nt+4][3] * c1b.y) * qscale;
                y[1][2] = (acc[mt][nt+4][2] * c1a.x + acc[mt][nt][2] * c1a.y) * qscale;
                y[1][3] = (acc[mt][nt+4][3] * c1b.x + acc[mt][nt][3] * c1b.y) * qscale;
                #pragma unroll
                for (int rr = 0; rr < 2; rr++) {
                    const size_t rbase = (size_t)(r0 + rr * 8) * DIM;
                    unsigned short h0, l0, h1, l1;
                    bf16_split(y[rr][0], h0, l0);
                    bf16_split(y[rr][1], h1, l1);
                    *(ushort2*)(Ch + rbase + col)      = make_ushort2(h0, h1);
                    *(ushort2*)(Cl + rbase + col)      = make_ushort2(l0, l1);
                    bf16_split(y[rr][2], h0, l0);
                    bf16_split(y[rr][3], h1, l1);
                    *(ushort2*)(Ch + rbase + col + 32) = make_ushort2(h0, h1);
                    *(ushort2*)(Cl + rbase + col + 32) = make_ushort2(l0, l1);
                }
            }
        }
        return;
    }

    #pragma unroll
    for (int mt = 0; mt < 2; mt++) {
        const int r0 = tm + wm + mt * 16 + (lane >> 2);
        #pragma unroll
        for (int nt = 0; nt < 8; nt++) {
            const int col = tn + wn + nt * 8 + (lane & 3) * 2;
            if (MODE == 0) {
                *(float2*)(C + (size_t)r0 * DIM + col) =
                    make_float2(acc[mt][nt][0], acc[mt][nt][1]);
                *(float2*)(C + (size_t)(r0 + 8) * DIM + col) =
                    make_float2(acc[mt][nt][2], acc[mt][nt][3]);
            } else {
                unsigned short h0, l0, h1, l1;
                bf16_split(acc[mt][nt][0], h0, l0);
                bf16_split(acc[mt][nt][1], h1, l1);
                *(ushort2*)(Ch + (size_t)r0 * DIM + col) = make_ushort2(h0, h1);
                *(ushort2*)(Cl + (size_t)r0 * DIM + col) = make_ushort2(l0, l1);
                bf16_split(acc[mt][nt][2], h0, l0);
                bf16_split(acc[mt][nt][3], h1, l1);
                *(ushort2*)(Ch + (size_t)(r0 + 8) * DIM + col) = make_ushort2(h0, h1);
                *(ushort2*)(Cl + (size_t)(r0 + 8) * DIM + col) = make_ushort2(l0, l1);
            }
        }
    }
}

// Q scale folds 1/sqrt(HDIM) AND log2(e): flash computes exp2(s) == exp(q.k/8).
#define QSCALE (0.125f * 1.4426950408889634f)

__global__ void __launch_bounds__(256, 1) hmma_qkv_kernel()
{
    const int z = blockIdx.z;
    if (z == 0)
        hmma_gemm_body<2>(g_Xh, g_Xl, g_Wh[0], g_Wl[0], nullptr, g_Qh, g_Ql, QSCALE);
    else if (z == 1)
        hmma_gemm_body<2>(g_Xh, g_Xl, g_Wh[1], g_Wl[1], nullptr, g_Kh, g_Kl, 1.0f);
    else
        hmma_gemm_body<1>(g_Xh, g_Xl, g_Wh[2], g_Wl[2], nullptr, g_Vh, g_Vl, 1.0f);
}

__global__ void __launch_bounds__(256, 1) hmma_oproj_kernel(float* __restrict__ out)
{
    hmma_gemm_body<0>(g_Ah, g_Al, g_Wh[3], g_Wl[3], out, nullptr, nullptr, 1.0f);
}

// ---------------------------------------------------------------------------
// HMMA flash attention (R16): K-tile widened 64 -> 128 keys per iteration
// (halves softmax reductions / barriers / loop overhead; MMA and exp counts
// unchanged). cp.async double-buffered K/V stages, trans-V ldmatrix,
// log2-domain static softmax with interleaved pack+PV.
// ---------------------------------------------------------------------------
#define FP          72
#define FQT         (128 * FP)                   // 9216 elems (one Q tile)
#define FVT_B       (128 * FP * 2)               // 18432 bytes (128-row tile)
#define STG_B       (4 * FVT_B)                  // 73728 bytes (Kh,Kl,Vh,Vl)
#define FSMEM_BYTES (2 * FQT * 2 + 2 * STG_B)    // 36864 + 147456 = 184320

__global__ void __launch_bounds__(256, 1) flash_hmma_kernel()
{
    extern __shared__ __nv_bfloat16 fsm[];
    __nv_bfloat16* sQh = fsm;
    __nv_bfloat16* sQl = fsm + FQT;

    const int tid  = threadIdx.x;
    const int wid  = tid >> 5;
    const int lane = tid & 31;
    const int qt = blockIdx.x, h = blockIdx.y, b = blockIdx.z;
    const int q0 = b * SEQ + qt * 128;

    const uint32_t uQh = smem_to_u32(sQh);
    const uint32_t uQl = uQh + FQT * 2;
    uint32_t uStage[2];
    uStage[0] = uQh + 2 * FQT * 2;
    uStage[1] = uStage[0] + STG_B;

    // ---- load Q tile (persistent): 128 rows x 8 segs of 16B
    #pragma unroll
    for (int t = tid; t < 1024; t += 256) {
        int row = t >> 3, seg = t & 7;
        size_t go = (size_t)(q0 + row) * DIM + h * HDIM + seg * 8;
        *(uint4*)(sQh + row * FP + seg * 8) = *(const uint4*)(g_Qh + go);
        *(uint4*)(sQl + row * FP + seg * 8) = *(const uint4*)(g_Ql + go);
    }

    // cp.async K/V stage loader: 4 tiles x 128 rows x 128B.
    // thread -> (row = tid>>1, 64B half = (tid&1)*64), 4x16B per tile.
    const int crow = tid >> 1;
    const int cofs = (tid & 1) * 64;
    const __nv_bfloat16* gsrc[4] = { g_Kh, g_Kl, g_Vh, g_Vl };
    auto issue_stage = [&](int kt, int s) {
        const size_t go = (size_t)(b * SEQ + kt * 128 + crow) * DIM + h * HDIM;
        #pragma unroll
        for (int t = 0; t < 4; t++) {
            const char* gp = (const char*)(gsrc[t] + go) + cofs;
            uint32_t sp = uStage[s] + t * FVT_B + crow * 144 + cofs;
            CP_ASYNC_16(sp,      gp);
            CP_ASYNC_16(sp + 16, gp + 16);
            CP_ASYNC_16(sp + 32, gp + 32);
            CP_ASYNC_16(sp + 48, gp + 48);
        }
    };

    const int wm = wid * 16;
    const uint32_t a_off   = (uint32_t)(wm + (lane & 15)) * 144 + ((lane >> 4) & 1) * 16;
    const uint32_t b_off_k = (uint32_t)((lane & 7) + ((lane >> 4) & 1) * 8) * 144
                           + ((lane >> 3) & 1) * 16;
    const uint32_t b_off_v = (uint32_t)((lane & 7) + ((lane >> 3) & 1) * 8) * 144
                           + ((lane >> 4) & 1) * 16;

    float o[8][4];
    #pragma unroll
    for (int i = 0; i < 8; i++)
        #pragma unroll
        for (int j = 0; j < 4; j++) o[i][j] = 0.0f;
    float l0 = 0.0f, l1 = 0.0f;

    issue_stage(0, 0);
    CP_COMMIT();

    #pragma unroll 1
    for (int kt = 0; kt < SEQ / 128; kt++) {     // 16 iterations
        const int s = kt & 1;
        CP_WAIT0();
        __syncthreads();
        if (kt + 1 < SEQ / 128) { issue_stage(kt + 1, s ^ 1); CP_COMMIT(); }

        const uint32_t uKh = uStage[s];
        const uint32_t uKl = uStage[s] + FVT_B;
        const uint32_t uVh = uStage[s] + 2 * FVT_B;
        const uint32_t uVl = uStage[s] + 3 * FVT_B;

        // ---- S = Q K^T over 128 keys (3 split passes); log2 domain
        float sc[16][4];
        #pragma unroll
        for (int i = 0; i < 16; i++)
            #pragma unroll
            for (int j = 0; j < 4; j++) sc[i][j] = 0.0f;

        #pragma unroll
        for (int ks = 0; ks < 4; ks++) {
            uint32_t ah[4], al[4];
            ldsm_x4(uQh + a_off + ks * 32, ah);
            ldsm_x4(uQl + a_off + ks * 32, al);
            #pragma unroll
            for (int nt2 = 0; nt2 < 8; nt2++) {
                uint32_t th[4], tl[4];
                ldsm_x4(uKh + b_off_k + nt2 * 2304 + ks * 32, th);
                ldsm_x4(uKl + b_off_k + nt2 * 2304 + ks * 32, tl);
                mma_bf16(sc[2*nt2],   ah, th);     mma_bf16(sc[2*nt2],   ah, tl);
                mma_bf16(sc[2*nt2],   al, th);
                mma_bf16(sc[2*nt2+1], ah, th + 2); mma_bf16(sc[2*nt2+1], ah, tl + 2);
                mma_bf16(sc[2*nt2+1], al, th + 2);
            }
        }

        // ---- interleaved softmax pack + PV over 8 key-slices of 16
        float rs0 = 0.0f, rs1 = 0.0f;
        #pragma unroll
        for (int ks = 0; ks < 8; ks++) {
            uint32_t aPh[4], aPl[4];
            #pragma unroll
            for (int hh = 0; hh < 2; hh++) {
                const int nf = 2 * ks + hh;
                float e00 = ex2f(sc[nf][0]);
                float e01 = ex2f(sc[nf][1]);
                float e10 = ex2f(sc[nf][2]);
                float e11 = ex2f(sc[nf][3]);
                rs0 += e00 + e01;
                rs1 += e10 + e11;
                unsigned short h00, l00, h01, l01, h10, l10, h11, l11;
                bf16_split(e00, h00, l00); bf16_split(e01, h01, l01);
                bf16_split(e10, h10, l10); bf16_split(e11, h11, l11);
                aPh[2*hh]   = ((uint32_t)h01 << 16) | h00;
                aPh[2*hh+1] = ((uint32_t)h11 << 16) | h10;
                aPl[2*hh]   = ((uint32_t)l01 << 16) | l00;
                aPl[2*hh+1] = ((uint32_t)l11 << 16) | l10;
            }
            #pragma unroll
            for (int nt2 = 0; nt2 < 4; nt2++) {
                uint32_t th[4], tl[4];
                ldsm_x4_trans(uVh + b_off_v + ks * 2304 + nt2 * 32, th);
                ldsm_x4_trans(uVl + b_off_v + ks * 2304 + nt2 * 32, tl);
                mma_bf16(o[2*nt2],   aPh, th);     mma_bf16(o[2*nt2],   aPh, tl);
                mma_bf16(o[2*nt2],   aPl, th);
                mma_bf16(o[2*nt2+1], aPh, th + 2); mma_bf16(o[2*nt2+1], aPh, tl + 2);
                mma_bf16(o[2*nt2+1], aPl, th + 2);
            }
        }
        rs0 += __shfl_xor_sync(0xffffffffu, rs0, 1);
        rs0 += __shfl_xor_sync(0xffffffffu, rs0, 2);
        rs1 += __shfl_xor_sync(0xffffffffu, rs1, 1);
        rs1 += __shfl_xor_sync(0xffffffffu, rs1, 2);
        l0 += rs0;
        l1 += rs1;
    }

    // ---- epilogue: normalize, write bf16 hi/lo attention output
    const float inv0 = 1.0f / l0, inv1 = 1.0f / l1;
    const int r0 = q0 + wm + (lane >> 2);
    #pragma unroll
    for (int nf = 0; nf < 8; nf++) {
        const int col = h * HDIM + nf * 8 + (lane & 3) * 2;
        unsigned short h0, lo0, h1, lo1;
        bf16_split(o[nf][0] * inv0, h0, lo0);
        bf16_split(o[nf][1] * inv0, h1, lo1);
        *(ushort2*)(g_Ah + (size_t)r0 * DIM + col) = make_ushort2(h0, h1);
        *(ushort2*)(g_Al + (size_t)r0 * DIM + col) = make_ushort2(lo0, lo1);
        bf16_split(o[nf][2] * inv1, h0, lo0);
        bf16_split(o[nf][3] * inv1, h1, lo1);
        *(ushort2*)(g_Ah + (size_t)(r0 + 8) * DIM + col) = make_ushort2(h0, h1);
        *(ushort2*)(g_Al + (size_t)(r0 + 8) * DIM + col) = make_ushort2(lo0, lo1);
    }
}

// ---------------------------------------------------------------------------
extern "C" void kernel_launch(void* const* d_in, const int* in_sizes, int n_in,
                              void* d_out, int out_size)
{
    const float* x  = (const float*)d_in[0];
    const float* Wq = (const float*)d_in[1];
    const float* Wk = (const float*)d_in[2];
    const float* Wv = (const float*)d_in[3];
    const float* Wo = (const float*)d_in[4];
    float* out = (float*)d_out;

    (void)in_sizes; (void)n_in; (void)out_size;

    cudaFuncSetAttribute(hmma_qkv_kernel,
                         cudaFuncAttributeMaxDynamicSharedMemorySize, SMEM_DYN);
    cudaFuncSetAttribute(hmma_oproj_kernel,
                         cudaFuncAttributeMaxDynamicSharedMemorySize, SMEM_DYN);
    cudaFuncSetAttribute(flash_hmma_kernel,
                         cudaFuncAttributeMaxDynamicSharedMemorySize, FSMEM_BYTES);

    __nv_bfloat16 *xh, *xl;
    cudaGetSymbolAddress((void**)&xh, g_Xh);
    cudaGetSymbolAddress((void**)&xl, g_Xl);

    const int nX = ROWS * DIM;      // 4M

    // 0) Rope cos/sin table
    rope_table_kernel<<<SEQ * 32 / 256, 256>>>();

    // 1) Split inputs into bf16 hi/lo
    split_kernel<<<nX / 4 / 256, 256>>>(x, xh, xl, nX);
    split_w4_kernel<<<4 * DIM * DIM / 4 / 256, 256>>>(Wq, Wk, Wv, Wo);

    // 2) Q,K,V projections; Q/K epilogues apply RoPE+scale+split in-register
    hmma_qkv_kernel<<<dim3(DIM / 128, ROWS / 128, 3), 256, SMEM_DYN>>>();

    // 3) Attention on HMMA (128-key tiles)
    flash_hmma_kernel<<<dim3(SEQ / 128, NHEAD, BATCH), 256, FSMEM_BYTES>>>();

    // 4) Output projection
    hmma_oproj_kernel<<<dim3(DIM / 128, ROWS / 128), 256, SMEM_DYN>>>(out);
}

// round 17
// speedup vs baseline: 1.1380x; 1.0000x over previous
#include <cuda_runtime.h>
#include <cuda_bf16.h>
#include <math.h>
#include <stdint.h>

#define DIM   1024
#define NHEAD 16
#define HDIM  64
#define BATCH 2
#define SEQ   2048
#define ROWS  (BATCH * SEQ)   // 4096

// ---------------------------------------------------------------------------
// Helpers (base-target PTX only: ldmatrix + mma.sync + cp.async)
// ---------------------------------------------------------------------------
__device__ __forceinline__ uint32_t smem_to_u32(const void* smem_ptr) {
    uint32_t addr;
    asm("{ .reg .u64 tmp; cvta.to.shared.u64 tmp, %1; cvt.u32.u64 %0, tmp; }"
        : "=r"(addr) : "l"(smem_ptr));
    return addr;
}

__device__ __forceinline__ void ldsm_x4(uint32_t addr, uint32_t* r) {
    asm volatile("ldmatrix.sync.aligned.m8n8.x4.shared.b16 {%0,%1,%2,%3}, [%4];"
        : "=r"(r[0]), "=r"(r[1]), "=r"(r[2]), "=r"(r[3]) : "r"(addr));
}

__device__ __forceinline__ void ldsm_x4_trans(uint32_t addr, uint32_t* r) {
    asm volatile("ldmatrix.sync.aligned.m8n8.x4.trans.shared.b16 {%0,%1,%2,%3}, [%4];"
        : "=r"(r[0]), "=r"(r[1]), "=r"(r[2]), "=r"(r[3]) : "r"(addr));
}

// D += A * B, bf16 inputs, fp32 accumulate (m16n8k16)
__device__ __forceinline__ void mma_bf16(float* d, const uint32_t* a,
                                         const uint32_t* b) {
    asm volatile(
        "mma.sync.aligned.m16n8k16.row.col.f32.bf16.bf16.f32 "
        "{%0,%1,%2,%3}, {%4,%5,%6,%7}, {%8,%9}, {%0,%1,%2,%3};"
        : "+f"(d[0]), "+f"(d[1]), "+f"(d[2]), "+f"(d[3])
        : "r"(a[0]), "r"(a[1]), "r"(a[2]), "r"(a[3]), "r"(b[0]), "r"(b[1]));
}

#define CP_ASYNC_16(saddr, gptr) \
    asm volatile("cp.async.cg.shared.global [%0], [%1], 16;" \
        :: "r"((uint32_t)(saddr)), "l"(gptr) : "memory")
#define CP_COMMIT() asm volatile("cp.async.commit_group;" ::: "memory")
#define CP_WAIT0()  asm volatile("cp.async.wait_group 0;" ::: "memory")

// raw exp2 (scores are pre-scaled by log2(e) via the Q projection epilogue)
__device__ __forceinline__ float ex2f(float x) {
    float y;
    asm("ex2.approx.f32 %0, %1;" : "=f"(y) : "f"(x));
    return y;
}

// hi/lo bf16 split of one fp32
__device__ __forceinline__ void bf16_split(float x, unsigned short& h,
                                           unsigned short& l) {
    __nv_bfloat16 hb = __float2bfloat16(x);
    __nv_bfloat16 lb = __float2bfloat16(x - __bfloat162float(hb));
    h = __bfloat16_as_ushort(hb);
    l = __bfloat16_as_ushort(lb);
}

// ---------------------------------------------------------------------------
// Scratch (allocation-free rule: __device__ globals)
// ---------------------------------------------------------------------------
__device__ __nv_bfloat16 g_Qh[ROWS * DIM], g_Ql[ROWS * DIM];
__device__ __nv_bfloat16 g_Kh[ROWS * DIM], g_Kl[ROWS * DIM];
__device__ __nv_bfloat16 g_Vh[ROWS * DIM], g_Vl[ROWS * DIM];
__device__ __nv_bfloat16 g_Xh[ROWS * DIM], g_Xl[ROWS * DIM];
__device__ __nv_bfloat16 g_Ah[ROWS * DIM], g_Al[ROWS * DIM];
__device__ __nv_bfloat16 g_Wh[4][DIM * DIM], g_Wl[4][DIM * DIM];  // q,k,v,o
__device__ float2 g_rope[SEQ * 32];   // (cos, sin) per (s, p)

// ---------------------------------------------------------------------------
// Rope table: one thread per (s, p) — 65536 distinct pairs.
// ---------------------------------------------------------------------------
__global__ void rope_table_kernel()
{
    int i = blockIdx.x * blockDim.x + threadIdx.x;
    int p = i & 31, s = i >> 5;
    float inv_freq = (float)exp((double)p * (-0.28782313662425574)); // 10000^(-p/32)
    float ang = (float)s * inv_freq;
    float sn, cs;
    sincosf(ang, &sn, &cs);
    g_rope[i] = make_float2(cs, sn);
}

// ---------------------------------------------------------------------------
// fp32 -> (bf16 hi, bf16 lo) splits
// ---------------------------------------------------------------------------
__global__ void split_kernel(const float* __restrict__ src,
                             __nv_bfloat16* __restrict__ hi,
                             __nv_bfloat16* __restrict__ lo, int n)
{
    int i = (blockIdx.x * blockDim.x + threadIdx.x) * 4;
    if (i >= n) return;
    float4 x = *(const float4*)(src + i);
    float xs[4] = {x.x, x.y, x.z, x.w};
    unsigned short hs[4], ls[4];
    #pragma unroll
    for (int k = 0; k < 4; k++) bf16_split(xs[k], hs[k], ls[k]);
    *(ushort4*)(hi + i) = make_ushort4(hs[0], hs[1], hs[2], hs[3]);
    *(ushort4*)(lo + i) = make_ushort4(ls[0], ls[1], ls[2], ls[3]);
}

__global__ void split_w4_kernel(const float* __restrict__ Wq,
                                const float* __restrict__ Wk,
                                const float* __restrict__ Wv,
                                const float* __restrict__ Wo)
{
    int i = (blockIdx.x * blockDim.x + threadIdx.x) * 4;
    const int w = i >> 20;
    const int j = i & ((DIM * DIM) - 1);
    const float* src = (w == 0) ? Wq : (w == 1) ? Wk : (w == 2) ? Wv : Wo;
    float4 x = *(const float4*)(src + j);
    float xs[4] = {x.x, x.y, x.z, x.w};
    unsigned short hs[4], ls[4];
    #pragma unroll
    for (int k = 0; k < 4; k++) bf16_split(xs[k], hs[k], ls[k]);
    *(ushort4*)(&g_Wh[0][0] + i) = make_ushort4(hs[0], hs[1], hs[2], hs[3]);
    *(ushort4*)(&g_Wl[0][0] + i) = make_ushort4(ls[0], ls[1], ls[2], ls[3]);
}

// ---------------------------------------------------------------------------
// HMMA NT GEMM — exact R14 body (register prefetch; measured 238us qkv).
// MODE 0: fp32 C. MODE 1: bf16 hi/lo C. MODE 2: RoPE+scale+hi/lo C.
// ---------------------------------------------------------------------------
#define BK          32
#define PITCH       40
#define TILE_ELEMS  (128 * PITCH)
#define STAGE_ELEMS (4 * TILE_ELEMS)
#define STAGE_BYTES (STAGE_ELEMS * 2)           // 40960
#define SMEM_DYN    (2 * STAGE_BYTES)           // 81920

template <int MODE>
__device__ __forceinline__ void hmma_gemm_body(const __nv_bfloat16* __restrict__ Ahg,
                                               const __nv_bfloat16* __restrict__ Alg,
                                               const __nv_bfloat16* __restrict__ Bhg,
                                               const __nv_bfloat16* __restrict__ Blg,
                                               float* __restrict__ C,
                                               __nv_bfloat16* __restrict__ Ch,
                                               __nv_bfloat16* __restrict__ Cl,
                                               float qscale)
{
    extern __shared__ __nv_bfloat16 sm[];
    const uint32_t smbase = smem_to_u32(sm);

    const int tid  = threadIdx.x;
    const int wid  = tid >> 5;
    const int lane = tid & 31;
    const int tm   = blockIdx.y * 128;
    const int tn   = blockIdx.x * 128;

    const int grow = tid >> 2;
    const int gseg = tid & 3;
    const __nv_bfloat16* pAh = Ahg + (size_t)(tm + grow) * DIM + gseg * 8;
    const __nv_bfloat16* pAl = Alg + (size_t)(tm + grow) * DIM + gseg * 8;
    const __nv_bfloat16* pBh = Bhg + (size_t)(tn + grow) * DIM + gseg * 8;
    const __nv_bfloat16* pBl = Blg + (size_t)(tn + grow) * DIM + gseg * 8;
    const size_t rstep = (size_t)64 * DIM;
    const int so = grow * PITCH + gseg * 8;

    const int wm = (wid & 3) * 32;
    const int wn = (wid >> 2) * 64;

    const uint32_t a_off = (uint32_t)(wm + (lane & 15)) * 80 + ((lane >> 4) & 1) * 16;
    const uint32_t b_off = (uint32_t)(wn + (lane & 7) + ((lane >> 4) & 1) * 8) * 80
                         + ((lane >> 3) & 1) * 16;

    float acc[2][8][4];
    #pragma unroll
    for (int i = 0; i < 2; i++)
        #pragma unroll
        for (int j = 0; j < 8; j++)
            #pragma unroll
            for (int k = 0; k < 4; k++) acc[i][j][k] = 0.0f;

    uint4 v[8];
    v[0] = *(const uint4*)(pAh);  v[1] = *(const uint4*)(pAh + rstep);
    v[2] = *(const uint4*)(pAl);  v[3] = *(const uint4*)(pAl + rstep);
    v[4] = *(const uint4*)(pBh);  v[5] = *(const uint4*)(pBh + rstep);
    v[6] = *(const uint4*)(pBl);  v[7] = *(const uint4*)(pBl + rstep);
    {
        __nv_bfloat16* st = sm;
        *(uint4*)(st + so)                           = v[0];
        *(uint4*)(st + so + 64 * PITCH)              = v[1];
        *(uint4*)(st + TILE_ELEMS + so)              = v[2];
        *(uint4*)(st + TILE_ELEMS + so + 64*PITCH)   = v[3];
        *(uint4*)(st + 2*TILE_ELEMS + so)            = v[4];
        *(uint4*)(st + 2*TILE_ELEMS + so + 64*PITCH) = v[5];
        *(uint4*)(st + 3*TILE_ELEMS + so)            = v[6];
        *(uint4*)(st + 3*TILE_ELEMS + so + 64*PITCH) = v[7];
    }
    __syncthreads();

    const int NCH = DIM / BK;   // 32
    #pragma unroll 1
    for (int c = 0; c < NCH; c++) {
        const int s = c & 1;
        if (c + 1 < NCH) {
            const size_t k = (size_t)(c + 1) * BK;
            v[0] = *(const uint4*)(pAh + k);  v[1] = *(const uint4*)(pAh + rstep + k);
            v[2] = *(const uint4*)(pAl + k);  v[3] = *(const uint4*)(pAl + rstep + k);
            v[4] = *(const uint4*)(pBh + k);  v[5] = *(const uint4*)(pBh + rstep + k);
            v[6] = *(const uint4*)(pBl + k);  v[7] = *(const uint4*)(pBl + rstep + k);
        }

        const uint32_t sb = smbase + s * STAGE_BYTES;
        #pragma unroll
        for (int ks = 0; ks < 2; ks++) {
            uint32_t ah[2][4], al_[2][4], bh[8][2], bl_[8][2];
            #pragma unroll
            for (int mt = 0; mt < 2; mt++) {
                ldsm_x4(sb + a_off + mt * 1280 + ks * 32, ah[mt]);
                ldsm_x4(sb + 10240 + a_off + mt * 1280 + ks * 32, al_[mt]);
            }
            #pragma unroll
            for (int nt2 = 0; nt2 < 4; nt2++) {
                uint32_t t[4];
                ldsm_x4(sb + 20480 + b_off + nt2 * 1280 + ks * 32, t);
                bh[2*nt2][0] = t[0]; bh[2*nt2][1] = t[1];
                bh[2*nt2+1][0] = t[2]; bh[2*nt2+1][1] = t[3];
                ldsm_x4(sb + 30720 + b_off + nt2 * 1280 + ks * 32, t);
                bl_[2*nt2][0] = t[0]; bl_[2*nt2][1] = t[1];
                bl_[2*nt2+1][0] = t[2]; bl_[2*nt2+1][1] = t[3];
            }
            #pragma unroll
            for (int mt = 0; mt < 2; mt++)
                #pragma unroll
                for (int nt = 0; nt < 8; nt++) {
                    mma_bf16(acc[mt][nt], ah[mt],  bh[nt]);
                    mma_bf16(acc[mt][nt], ah[mt],  bl_[nt]);
                    mma_bf16(acc[mt][nt], al_[mt], bh[nt]);
                }
        }

        if (c + 1 < NCH) {
            __nv_bfloat16* st = sm + (s ^ 1) * STAGE_ELEMS;
            *(uint4*)(st + so)                           = v[0];
            *(uint4*)(st + so + 64 * PITCH)              = v[1];
            *(uint4*)(st + TILE_ELEMS + so)              = v[2];
            *(uint4*)(st + TILE_ELEMS + so + 64*PITCH)   = v[3];
            *(uint4*)(st + 2*TILE_ELEMS + so)            = v[4];
            *(uint4*)(st + 2*TILE_ELEMS + so + 64*PITCH) = v[5];
            *(uint4*)(st + 3*TILE_ELEMS + so)            = v[6];
            *(uint4*)(st + 3*TILE_ELEMS + so + 64*PITCH) = v[7];
            __syncthreads();
        }
    }

    if (MODE == 2) {
        #pragma unroll
        for (int mt = 0; mt < 2; mt++) {
            const int r0 = tm + wm + mt * 16 + (lane >> 2);
            const int s0 = r0 & (SEQ - 1);
            const int s1 = (r0 + 8) & (SEQ - 1);
            #pragma unroll
            for (int nt = 0; nt < 4; nt++) {
                const int p   = nt * 8 + (lane & 3) * 2;
                const int col = tn + wn + p;
                const float2 c0a = g_rope[s0 * 32 + p];
                const float2 c0b = g_rope[s0 * 32 + p + 1];
                const float2 c1a = g_rope[s1 * 32 + p];
                const float2 c1b = g_rope[s1 * 32 + p + 1];
                float y[2][4];
                y[0][0] = (acc[mt][nt][0] * c0a.x - acc[mt][nt+4][0] * c0a.y) * qscale;
                y[0][1] = (acc[mt][nt][1] * c0b.x - acc[mt][nt+4][1] * c0b.y) * qscale;
                y[0][2] = (acc[mt][nt+4][0] * c0a.x + acc[mt][nt][0] * c0a.y) * qscale;
                y[0][3] = (acc[mt][nt+4][1] * c0b.x + acc[mt][nt][1] * c0b.y) * qscale;
                y[1][0] = (acc[mt][nt][2] * c1a.x - acc[mt][nt+4][2] * c1a.y) * qscale;
                y[1][1] = (acc[mt][nt][3] * c1b.x - acc[mt][nt+4][3] * c1b.y) * qscale;
                y[1][2] = (acc[mt][nt+4][2] * c1a.x + acc[mt][nt][2] * c1a.y) * qscale;
                y[1][3] = (acc[mt][nt+4][3] * c1b.x + acc[mt][nt][3] * c1b.y) * qscale;
                #pragma unroll
                for (int rr = 0; rr < 2; rr++) {
                    const size_t rbase = (size_t)(r0 + rr * 8) * DIM;
                    unsigned short h0, l0, h1, l1;
                    bf16_split(y[rr][0], h0, l0);
                    bf16_split(y[rr][1], h1, l1);
                    *(ushort2*)(Ch + rbase + col)      = make_ushort2(h0, h1);
                    *(ushort2*)(Cl + rbase + col)      = make_ushort2(l0, l1);
                    bf16_split(y[rr][2], h0, l0);
                    bf16_split(y[rr][3], h1, l1);
                    *(ushort2*)(Ch + rbase + col + 32) = make_ushort2(h0, h1);
                    *(ushort2*)(Cl + rbase + col + 32) = make_ushort2(l0, l1);
                }
            }
        }
        return;
    }

    #pragma unroll
    for (int mt = 0; mt < 2; mt++) {
        const int r0 = tm + wm + mt * 16 + (lane >> 2);
        #pragma unroll
        for (int nt = 0; nt < 8; nt++) {
            const int col = tn + wn + nt * 8 + (lane & 3) * 2;
            if (MODE == 0) {
                *(float2*)(C + (size_t)r0 * DIM + col) =
                    make_float2(acc[mt][nt][0], acc[mt][nt][1]);
                *(float2*)(C + (size_t)(r0 + 8) * DIM + col) =
                    make_float2(acc[mt][nt][2], acc[mt][nt][3]);
            } else {
                unsigned short h0, l0, h1, l1;
                bf16_split(acc[mt][nt][0], h0, l0);
                bf16_split(acc[mt][nt][1], h1, l1);
                *(ushort2*)(Ch + (size_t)r0 * DIM + col) = make_ushort2(h0, h1);
                *(ushort2*)(Cl + (size_t)r0 * DIM + col) = make_ushort2(l0, l1);
                bf16_split(acc[mt][nt][2], h0, l0);
                bf16_split(acc[mt][nt][3], h1, l1);
                *(ushort2*)(Ch + (size_t)(r0 + 8) * DIM + col) = make_ushort2(h0, h1);
                *(ushort2*)(Cl + (size_t)(r0 + 8) * DIM + col) = make_ushort2(l0, l1);
            }
        }
    }
}

// Q scale folds 1/sqrt(HDIM) AND log2(e): flash computes exp2(s) == exp(q.k/8).
#define QSCALE (0.125f * 1.4426950408889634f)

__global__ void __launch_bounds__(256, 1) hmma_qkv_kernel()
{
    const int z = blockIdx.z;
    if (z == 0)
        hmma_gemm_body<2>(g_Xh, g_Xl, g_Wh[0], g_Wl[0], nullptr, g_Qh, g_Ql, QSCALE);
    else if (z == 1)
        hmma_gemm_body<2>(g_Xh, g_Xl, g_Wh[1], g_Wl[1], nullptr, g_Kh, g_Kl, 1.0f);
    else
        hmma_gemm_body<1>(g_Xh, g_Xl, g_Wh[2], g_Wl[2], nullptr, g_Vh, g_Vl, 1.0f);
}

__global__ void __launch_bounds__(256, 1) hmma_oproj_kernel(float* __restrict__ out)
{
    hmma_gemm_body<0>(g_Ah, g_Al, g_Wh[3], g_Wl[3], out, nullptr, nullptr, 1.0f);
}

// ---------------------------------------------------------------------------
// HMMA flash attention (R16): K-tile widened 64 -> 128 keys per iteration
// (halves softmax reductions / barriers / loop overhead; MMA and exp counts
// unchanged). cp.async double-buffered K/V stages, trans-V ldmatrix,
// log2-domain static softmax with interleaved pack+PV.
// ---------------------------------------------------------------------------
#define FP          72
#define FQT         (128 * FP)                   // 9216 elems (one Q tile)
#define FVT_B       (128 * FP * 2)               // 18432 bytes (128-row tile)
#define STG_B       (4 * FVT_B)                  // 73728 bytes (Kh,Kl,Vh,Vl)
#define FSMEM_BYTES (2 * FQT * 2 + 2 * STG_B)    // 36864 + 147456 = 184320

__global__ void __launch_bounds__(256, 1) flash_hmma_kernel()
{
    extern __shared__ __nv_bfloat16 fsm[];
    __nv_bfloat16* sQh = fsm;
    __nv_bfloat16* sQl = fsm + FQT;

    const int tid  = threadIdx.x;
    const int wid  = tid >> 5;
    const int lane = tid & 31;
    const int qt = blockIdx.x, h = blockIdx.y, b = blockIdx.z;
    const int q0 = b * SEQ + qt * 128;

    const uint32_t uQh = smem_to_u32(sQh);
    const uint32_t uQl = uQh + FQT * 2;
    uint32_t uStage[2];
    uStage[0] = uQh + 2 * FQT * 2;
    uStage[1] = uStage[0] + STG_B;

    // ---- load Q tile (persistent): 128 rows x 8 segs of 16B
    #pragma unroll
    for (int t = tid; t < 1024; t += 256) {
        int row = t >> 3, seg = t & 7;
        size_t go = (size_t)(q0 + row) * DIM + h * HDIM + seg * 8;
        *(uint4*)(sQh + row * FP + seg * 8) = *(const uint4*)(g_Qh + go);
        *(uint4*)(sQl + row * FP + seg * 8) = *(const uint4*)(g_Ql + go);
    }

    // cp.async K/V stage loader: 4 tiles x 128 rows x 128B.
    // thread -> (row = tid>>1, 64B half = (tid&1)*64), 4x16B per tile.
    const int crow = tid >> 1;
    const int cofs = (tid & 1) * 64;
    const __nv_bfloat16* gsrc[4] = { g_Kh, g_Kl, g_Vh, g_Vl };
    auto issue_stage = [&](int kt, int s) {
        const size_t go = (size_t)(b * SEQ + kt * 128 + crow) * DIM + h * HDIM;
        #pragma unroll
        for (int t = 0; t < 4; t++) {
            const char* gp = (const char*)(gsrc[t] + go) + cofs;
            uint32_t sp = uStage[s] + t * FVT_B + crow * 144 + cofs;
            CP_ASYNC_16(sp,      gp);
            CP_ASYNC_16(sp + 16, gp + 16);
            CP_ASYNC_16(sp + 32, gp + 32);
            CP_ASYNC_16(sp + 48, gp + 48);
        }
    };

    const int wm = wid * 16;
    const uint32_t a_off   = (uint32_t)(wm + (lane & 15)) * 144 + ((lane >> 4) & 1) * 16;
    const uint32_t b_off_k = (uint32_t)((lane & 7) + ((lane >> 4) & 1) * 8) * 144
                           + ((lane >> 3) & 1) * 16;
    const uint32_t b_off_v = (uint32_t)((lane & 7) + ((lane >> 3) & 1) * 8) * 144
                           + ((lane >> 4) & 1) * 16;

    float o[8][4];
    #pragma unroll
    for (int i = 0; i < 8; i++)
        #pragma unroll
        for (int j = 0; j < 4; j++) o[i][j] = 0.0f;
    float l0 = 0.0f, l1 = 0.0f;

    issue_stage(0, 0);
    CP_COMMIT();

    #pragma unroll 1
    for (int kt = 0; kt < SEQ / 128; kt++) {     // 16 iterations
        const int s = kt & 1;
        CP_WAIT0();
        __syncthreads();
        if (kt + 1 < SEQ / 128) { issue_stage(kt + 1, s ^ 1); CP_COMMIT(); }

        const uint32_t uKh = uStage[s];
        const uint32_t uKl = uStage[s] + FVT_B;
        const uint32_t uVh = uStage[s] + 2 * FVT_B;
        const uint32_t uVl = uStage[s] + 3 * FVT_B;

        // ---- S = Q K^T over 128 keys (3 split passes); log2 domain
        float sc[16][4];
        #pragma unroll
        for (int i = 0; i < 16; i++)
            #pragma unroll
            for (int j = 0; j < 4; j++) sc[i][j] = 0.0f;

        #pragma unroll
        for (int ks = 0; ks < 4; ks++) {
            uint32_t ah[4], al[4];
            ldsm_x4(uQh + a_off + ks * 32, ah);
            ldsm_x4(uQl + a_off + ks * 32, al);
            #pragma unroll
            for (int nt2 = 0; nt2 < 8; nt2++) {
                uint32_t th[4], tl[4];
                ldsm_x4(uKh + b_off_k + nt2 * 2304 + ks * 32, th);
                ldsm_x4(uKl + b_off_k + nt2 * 2304 + ks * 32, tl);
                mma_bf16(sc[2*nt2],   ah, th);     mma_bf16(sc[2*nt2],   ah, tl);
                mma_bf16(sc[2*nt2],   al, th);
                mma_bf16(sc[2*nt2+1], ah, th + 2); mma_bf16(sc[2*nt2+1], ah, tl + 2);
                mma_bf16(sc[2*nt2+1], al, th + 2);
            }
        }

        // ---- interleaved softmax pack + PV over 8 key-slices of 16
        float rs0 = 0.0f, rs1 = 0.0f;
        #pragma unroll
        for (int ks = 0; ks < 8; ks++) {
            uint32_t aPh[4], aPl[4];
            #pragma unroll
            for (int hh = 0; hh < 2; hh++) {
                const int nf = 2 * ks + hh;
                float e00 = ex2f(sc[nf][0]);
                float e01 = ex2f(sc[nf][1]);
                float e10 = ex2f(sc[nf][2]);
                float e11 = ex2f(sc[nf][3]);
                rs0 += e00 + e01;
                rs1 += e10 + e11;
                unsigned short h00, l00, h01, l01, h10, l10, h11, l11;
                bf16_split(e00, h00, l00); bf16_split(e01, h01, l01);
                bf16_split(e10, h10, l10); bf16_split(e11, h11, l11);
                aPh[2*hh]   = ((uint32_t)h01 << 16) | h00;
                aPh[2*hh+1] = ((uint32_t)h11 << 16) | h10;
                aPl[2*hh]   = ((uint32_t)l01 << 16) | l00;
                aPl[2*hh+1] = ((uint32_t)l11 << 16) | l10;
            }
            #pragma unroll
            for (int nt2 = 0; nt2 < 4; nt2++) {
                uint32_t th[4], tl[4];
                ldsm_x4_trans(uVh + b_off_v + ks * 2304 + nt2 * 32, th);
                ldsm_x4_trans(uVl + b_off_v + ks * 2304 + nt2 * 32, tl);
                mma_bf16(o[2*nt2],   aPh, th);     mma_bf16(o[2*nt2],   aPh, tl);
                mma_bf16(o[2*nt2],   aPl, th);
                mma_bf16(o[2*nt2+1], aPh, th + 2); mma_bf16(o[2*nt2+1], aPh, tl + 2);
                mma_bf16(o[2*nt2+1], aPl, th + 2);
            }
        }
        rs0 += __shfl_xor_sync(0xffffffffu, rs0, 1);
        rs0 += __shfl_xor_sync(0xffffffffu, rs0, 2);
        rs1 += __shfl_xor_sync(0xffffffffu, rs1, 1);
        rs1 += __shfl_xor_sync(0xffffffffu, rs1, 2);
        l0 += rs0;
        l1 += rs1;
    }

    // ---- epilogue: normalize, write bf16 hi/lo attention output
    const float inv0 = 1.0f / l0, inv1 = 1.0f / l1;
    const int r0 = q0 + wm + (lane >> 2);
    #pragma unroll
    for (int nf = 0; nf < 8; nf++) {
        const int col = h * HDIM + nf * 8 + (lane & 3) * 2;
        unsigned short h0, lo0, h1, lo1;
        bf16_split(o[nf][0] * inv0, h0, lo0);
        bf16_split(o[nf][1] * inv0, h1, lo1);
        *(ushort2*)(g_Ah + (size_t)r0 * DIM + col) = make_ushort2(h0, h1);
        *(ushort2*)(g_Al + (size_t)r0 * DIM + col) = make_ushort2(lo0, lo1);
        bf16_split(o[nf][2] * inv1, h0, lo0);
        bf16_split(o[nf][3] * inv1, h1, lo1);
        *(ushort2*)(g_Ah + (size_t)(r0 + 8) * DIM + col) = make_ushort2(h0, h1);
        *(ushort2*)(g_Al + (size_t)(r0 + 8) * DIM + col) = make_ushort2(lo0, lo1);
    }
}

// ---------------------------------------------------------------------------
extern "C" void kernel_launch(void* const* d_in, const int* in_sizes, int n_in,
                              void* d_out, int out_size)
{
    const float* x  = (const float*)d_in[0];
    const float* Wq = (const float*)d_in[1];
    const float* Wk = (const float*)d_in[2];
    const float* Wv = (const float*)d_in[3];
    const float* Wo = (const float*)d_in[4];
    float* out = (float*)d_out;

    (void)in_sizes; (void)n_in; (void)out_size;

    cudaFuncSetAttribute(hmma_qkv_kernel,
                         cudaFuncAttributeMaxDynamicSharedMemorySize, SMEM_DYN);
    cudaFuncSetAttribute(hmma_oproj_kernel,
                         cudaFuncAttributeMaxDynamicSharedMemorySize, SMEM_DYN);
    cudaFuncSetAttribute(flash_hmma_kernel,
                         cudaFuncAttributeMaxDynamicSharedMemorySize, FSMEM_BYTES);

    __nv_bfloat16 *xh, *xl;
    cudaGetSymbolAddress((void**)&xh, g_Xh);
    cudaGetSymbolAddress((void**)&xl, g_Xl);

    const int nX = ROWS * DIM;      // 4M

    // 0) Rope cos/sin table
    rope_table_kernel<<<SEQ * 32 / 256, 256>>>();

    // 1) Split inputs into bf16 hi/lo
    split_kernel<<<nX / 4 / 256, 256>>>(x, xh, xl, nX);
    split_w4_kernel<<<4 * DIM * DIM / 4 / 256, 256>>>(Wq, Wk, Wv, Wo);

    // 2) Q,K,V projections; Q/K epilogues apply RoPE+scale+split in-register
    hmma_qkv_kernel<<<dim3(DIM / 128, ROWS / 128, 3), 256, SMEM_DYN>>>();

    // 3) Attention on HMMA (128-key tiles)
    flash_hmma_kernel<<<dim3(SEQ / 128, NHEAD, BATCH), 256, FSMEM_BYTES>>>();

    // 4) Output projection
    hmma_oproj_kernel<<<dim3(DIM / 128, ROWS / 128), 256, SMEM_DYN>>>(out);
}